// round 1
// baseline (speedup 1.0000x reference)
#include <cuda_runtime.h>
#include <math.h>
#include <stdint.h>

#define BB 128
#define SS 1024
#define II 256
#define HH 512
#define G3 1536   // 3*H

// ---------------- device scratch (static allocation only) ----------------
__device__ float g_xproj[(size_t)BB * SS * G3];   // (B, S, 3H)  ~805 MB
__device__ float g_h[2][BB * HH];                 // double-buffered hidden state
__device__ unsigned g_bar;                        // software grid barrier counter

// ---------------- init: zero h0 and reset barrier (per replay) ----------------
__global__ void init_kernel() {
    int idx = blockIdx.x * blockDim.x + threadIdx.x;
    if (idx == 0) g_bar = 0u;
    for (int i = idx; i < BB * HH; i += gridDim.x * blockDim.x)
        g_h[0][i] = 0.0f;
}

// ---------------- x_proj GEMM: (B*S, I) x (I, 3H) + b_in ----------------
#define XBM 64
#define XBN 64
#define XBK 16

__global__ void __launch_bounds__(256) xproj_kernel(const float* __restrict__ A,
                                                    const float* __restrict__ W,
                                                    const float* __restrict__ bias) {
    __shared__ float As[XBK][68];     // transposed A tile, padded (float4-aligned rows)
    __shared__ float Bs[XBK][XBN];

    const int m0 = blockIdx.y * XBM;
    const int n0 = blockIdx.x * XBN;
    const int tid = threadIdx.x;
    const int tr = tid >> 4;          // 0..15
    const int tc = tid & 15;          // 0..15

    // staging indices
    const int am = tid >> 2;          // 0..63 (row within A tile)
    const int ak = (tid & 3) << 2;    // 0,4,8,12 (k offset, float4)
    const int bk = tid >> 4;          // 0..15
    const int bn = (tid & 15) << 2;   // 0..60

    float acc[4][4];
#pragma unroll
    for (int i = 0; i < 4; ++i)
#pragma unroll
        for (int j = 0; j < 4; ++j) acc[i][j] = 0.0f;

    for (int k0 = 0; k0 < II; k0 += XBK) {
        float4 av = *(const float4*)(A + (size_t)(m0 + am) * II + k0 + ak);
        As[ak + 0][am] = av.x;
        As[ak + 1][am] = av.y;
        As[ak + 2][am] = av.z;
        As[ak + 3][am] = av.w;
        *(float4*)&Bs[bk][bn] = *(const float4*)(W + (size_t)(k0 + bk) * G3 + n0 + bn);
        __syncthreads();

#pragma unroll
        for (int k = 0; k < XBK; ++k) {
            float4 a = *(const float4*)&As[k][tr << 2];
            float4 b = *(const float4*)&Bs[k][tc << 2];
            float ar[4] = {a.x, a.y, a.z, a.w};
            float br[4] = {b.x, b.y, b.z, b.w};
#pragma unroll
            for (int i = 0; i < 4; ++i)
#pragma unroll
                for (int j = 0; j < 4; ++j)
                    acc[i][j] += ar[i] * br[j];
        }
        __syncthreads();
    }

    float4 bb = *(const float4*)(bias + n0 + (tc << 2));
    float bbr[4] = {bb.x, bb.y, bb.z, bb.w};
#pragma unroll
    for (int i = 0; i < 4; ++i) {
        float4 v;
        v.x = acc[i][0] + bbr[0];
        v.y = acc[i][1] + bbr[1];
        v.z = acc[i][2] + bbr[2];
        v.w = acc[i][3] + bbr[3];
        *(float4*)(g_xproj + (size_t)(m0 + (tr << 2) + i) * G3 + n0 + (tc << 2)) = v;
    }
}

// ---------------- persistent GRU recurrence ----------------
// Grid: 128 CTAs = 8 row-tiles (16 batch rows) x 16 col-tiles (32 hidden cols x 3 gates).
// W_h slice (512 x 96 fp32 = 192 KB) stays in SMEM for all 1024 steps.
// Software grid barrier: guaranteed safe since 128 CTAs <= 148 SMs at 1 CTA/SM.

#define REC_SMEM ((HH * 96 + 16 * HH) * 4)   // 192KB W + 32KB h tile = 229376 B

__global__ void __launch_bounds__(128, 1) gru_kernel(const float* __restrict__ Wh,
                                                     const float* __restrict__ bias,
                                                     float* __restrict__ out) {
    extern __shared__ float sm[];
    float* Ws  = sm;            // [512][96], col c = gate*32 + j_local
    float* hsm = sm + HH * 96;  // [16][512]

    const int tid = threadIdx.x;
    const int ct = blockIdx.x & 15;     // hidden-column group
    const int rt = blockIdx.x >> 4;     // batch-row tile
    const int jbase = ct * 32;

    // Stage W_h slice once (reused 1024 steps)
    for (int idx = tid; idx < HH * 96; idx += 128) {
        int k = idx / 96;
        int c = idx - k * 96;
        int g = c >> 5;
        int j = c & 31;
        Ws[idx] = Wh[(size_t)k * G3 + g * HH + jbase + j];
    }

    const int rg = tid >> 4;         // 0..7  -> rows r0, r0+1
    const int jg = tid & 15;         // 0..15 -> cols j0, j0+1
    const int r0 = rg * 2;
    const int j0 = jbase + jg * 2;

    float bh[3][2];
#pragma unroll
    for (int g = 0; g < 3; ++g) {
        bh[g][0] = bias[G3 + g * HH + j0];
        bh[g][1] = bias[G3 + g * HH + j0 + 1];
    }
    __syncthreads();

    const int b0 = rt * 16;

    for (int s = 0; s < SS; ++s) {
        const float* hin = g_h[s & 1];
        float* hout = g_h[(s + 1) & 1];

        // Stage 16 x 512 h rows (bypass L1: written by other SMs last step)
#pragma unroll
        for (int t = 0; t < 16; ++t) {
            int idx = (t * 128 + tid) * 4;   // float index 0..8191
            float4 v = __ldcg((const float4*)(hin + (size_t)b0 * HH + idx));
            *(float4*)(hsm + idx) = v;
        }
        __syncthreads();

        float acc[2][3][2];
#pragma unroll
        for (int g = 0; g < 3; ++g) {
            acc[0][g][0] = bh[g][0]; acc[0][g][1] = bh[g][1];
            acc[1][g][0] = bh[g][0]; acc[1][g][1] = bh[g][1];
        }

        const float* hr0 = hsm + r0 * HH;
        const float* hr1 = hsm + (r0 + 1) * HH;

#pragma unroll 2
        for (int k = 0; k < HH; k += 4) {
            float4 h0v4 = *(const float4*)(hr0 + k);
            float4 h1v4 = *(const float4*)(hr1 + k);
            float h0a[4] = {h0v4.x, h0v4.y, h0v4.z, h0v4.w};
            float h1a[4] = {h1v4.x, h1v4.y, h1v4.z, h1v4.w};
#pragma unroll
            for (int kk = 0; kk < 4; ++kk) {
                const float* wrow = Ws + (k + kk) * 96 + jg * 2;
                float2 wr = *(const float2*)(wrow);
                float2 wz = *(const float2*)(wrow + 32);
                float2 wn = *(const float2*)(wrow + 64);
                float h0 = h0a[kk];
                float h1 = h1a[kk];
                acc[0][0][0] += h0 * wr.x; acc[0][0][1] += h0 * wr.y;
                acc[0][1][0] += h0 * wz.x; acc[0][1][1] += h0 * wz.y;
                acc[0][2][0] += h0 * wn.x; acc[0][2][1] += h0 * wn.y;
                acc[1][0][0] += h1 * wr.x; acc[1][0][1] += h1 * wr.y;
                acc[1][1][0] += h1 * wz.x; acc[1][1][1] += h1 * wz.y;
                acc[1][2][0] += h1 * wn.x; acc[1][2][1] += h1 * wn.y;
            }
        }

        // Gates + state update + outputs
#pragma unroll
        for (int ri = 0; ri < 2; ++ri) {
            int b = b0 + r0 + ri;
            const float* xp = g_xproj + ((size_t)b * SS + s) * G3;
            const float* hrow = hsm + (r0 + ri) * HH;
#pragma unroll
            for (int jj = 0; jj < 2; ++jj) {
                int j = j0 + jj;
                float xr = xp[j];
                float xz = xp[HH + j];
                float xn = xp[2 * HH + j];
                float rr = 1.0f / (1.0f + expf(-(xr + acc[ri][0][jj])));
                float zz = 1.0f / (1.0f + expf(-(xz + acc[ri][1][jj])));
                float nn = tanhf(xn + rr * acc[ri][2][jj]);
                float hold = hrow[j];
                float hnew = (1.0f - zz) * nn + zz * hold;
                out[((size_t)b * SS + s) * HH + j] = hnew;
                hout[(size_t)b * HH + j] = hnew;
                if (s == SS - 1)
                    out[(size_t)BB * SS * HH + (size_t)b * HH + j] = hnew;
            }
        }

        // ---- software grid barrier (monotonic counter) ----
        __threadfence();
        __syncthreads();
        if (tid == 0) {
            unsigned tgt = (unsigned)(s + 1) * 128u;
            atomicAdd(&g_bar, 1u);
            while (*(volatile unsigned*)&g_bar < tgt) {
                __nanosleep(32);
            }
        }
        __syncthreads();
        __threadfence();
    }
}

// ---------------- launch ----------------
extern "C" void kernel_launch(void* const* d_in, const int* in_sizes, int n_in,
                              void* d_out, int out_size) {
    const float* inputs = (const float*)d_in[0];   // (B, S, I)
    const float* W_in   = (const float*)d_in[1];   // (I, 3H)
    const float* W_h    = (const float*)d_in[2];   // (H, 3H)
    const float* bias   = (const float*)d_in[3];   // (6H,)
    float* out = (float*)d_out;

    init_kernel<<<64, 256>>>();

    dim3 xgrid(G3 / XBN, (BB * SS) / XBM);   // (24, 2048)
    xproj_kernel<<<xgrid, 256>>>(inputs, W_in, bias);

    cudaFuncSetAttribute(gru_kernel, cudaFuncAttributeMaxDynamicSharedMemorySize, REC_SMEM);
    gru_kernel<<<128, 128, REC_SMEM>>>(W_h, bias, out);
}

// round 3
// speedup vs baseline: 1.0752x; 1.0752x over previous
#include <cuda_runtime.h>
#include <math.h>
#include <stdint.h>

#define BB 128
#define SS 1024
#define II 256
#define HH 512
#define G3 1536   // 3*H

// ---------------- device scratch ----------------
__device__ float g_xproj[(size_t)BB * SS * G3];   // (B, S, 3H)
__device__ float g_h[2][BB * HH];                 // double-buffered hidden state
__device__ unsigned g_bar[8 * 64];                // per-row-group barrier counters (256B apart)

// ---------------- f32x2 helpers ----------------
__device__ __forceinline__ unsigned long long ffma2(unsigned long long a,
                                                    unsigned long long b,
                                                    unsigned long long c) {
    unsigned long long d;
    asm("fma.rn.f32x2 %0, %1, %2, %3;" : "=l"(d) : "l"(a), "l"(b), "l"(c));
    return d;
}
__device__ __forceinline__ unsigned long long pack2(float x, float y) {
    unsigned long long d;
    asm("mov.b64 %0, {%1, %2};" : "=l"(d) : "f"(x), "f"(y));
    return d;
}
__device__ __forceinline__ float sum2(unsigned long long v) {
    float a, b;
    asm("mov.b64 {%0, %1}, %2;" : "=f"(a), "=f"(b) : "l"(v));
    return a + b;
}

// ---------------- init: zero h0 and barrier counters ----------------
__global__ void init_kernel() {
    int idx = blockIdx.x * blockDim.x + threadIdx.x;
    if (idx < 8 * 64) g_bar[idx] = 0u;
    for (int i = idx; i < BB * HH; i += gridDim.x * blockDim.x)
        g_h[0][i] = 0.0f;
}

// ---------------- x_proj GEMM: (B*S, I) x (I, 3H) + b_in, f32x2 k-split ----------------
#define XPM 128
#define XPN 64
#define XPK 16

__global__ void __launch_bounds__(256, 2) xproj_kernel(const float* __restrict__ A,
                                                       const float* __restrict__ W,
                                                       const float* __restrict__ bias) {
    __shared__ float As[XPM * XPK];     // [m][k], stride 16
    __shared__ float Wt[XPN * 18];      // [n][k] transposed, stride 18 (conflict-free)

    const int m0 = blockIdx.y * XPM;
    const int n0 = blockIdx.x * XPN;
    const int tid = threadIdx.x;
    const int tm = tid >> 4;            // 0..15 -> 8 rows each
    const int tn = tid & 15;            // 0..15 -> cols {tn, tn+16, tn+32, tn+48}
    const int m_base = tm * 8;

    unsigned long long acc[8][4];
#pragma unroll
    for (int i = 0; i < 8; ++i)
#pragma unroll
        for (int j = 0; j < 4; ++j) acc[i][j] = 0ull;

    // staging indices
    const int sa_m = tid >> 2;          // 0..63
    const int sa_k = (tid & 3) << 2;    // 0,4,8,12
    const int sw_k = tid >> 4;          // 0..15
    const int sw_n = (tid & 15) << 2;   // 0..60

    for (int k0 = 0; k0 < II; k0 += XPK) {
        // stage A tile (128 x 16): 2 float4 per thread
#pragma unroll
        for (int q = 0; q < 2; ++q) {
            int m = sa_m + q * 64;
            *(float4*)&As[m * 16 + sa_k] =
                *(const float4*)(A + (size_t)(m0 + m) * II + k0 + sa_k);
        }
        // stage W tile transposed (16k x 64n -> Wt[n][k])
        {
            float4 w = *(const float4*)(W + (size_t)(k0 + sw_k) * G3 + n0 + sw_n);
            Wt[(sw_n + 0) * 18 + sw_k] = w.x;
            Wt[(sw_n + 1) * 18 + sw_k] = w.y;
            Wt[(sw_n + 2) * 18 + sw_k] = w.z;
            Wt[(sw_n + 3) * 18 + sw_k] = w.w;
        }
        __syncthreads();

#pragma unroll
        for (int kk = 0; kk < XPK; kk += 4) {
            ulonglong2 av[8];
#pragma unroll
            for (int i = 0; i < 8; ++i)
                av[i] = *(const ulonglong2*)&As[(m_base + i) * 16 + kk];
#pragma unroll
            for (int j = 0; j < 4; ++j) {
                const float* wp = &Wt[(tn + 16 * j) * 18 + kk];
                unsigned long long w0 = *(const unsigned long long*)(wp);
                unsigned long long w1 = *(const unsigned long long*)(wp + 2);
#pragma unroll
                for (int i = 0; i < 8; ++i) {
                    acc[i][j] = ffma2(av[i].x, w0, acc[i][j]);
                    acc[i][j] = ffma2(av[i].y, w1, acc[i][j]);
                }
            }
        }
        __syncthreads();
    }

    float bb[4];
#pragma unroll
    for (int j = 0; j < 4; ++j) bb[j] = bias[n0 + tn + 16 * j];

#pragma unroll
    for (int i = 0; i < 8; ++i) {
        float* orow = g_xproj + (size_t)(m0 + m_base + i) * G3 + n0 + tn;
#pragma unroll
        for (int j = 0; j < 4; ++j)
            orow[16 * j] = sum2(acc[i][j]) + bb[j];
    }
}

// ---------------- persistent GRU recurrence (f32x2 k-split) ----------------
// 128 CTAs = 8 row-tiles (16 batch rows) x 16 col-tiles (32 hidden cols x 3 gates).
// W_h slice transposed in SMEM: Ws[c][k], c = gate*32 + j_local, stride 516.
// Thread (rg 0..7, jg 0..15): 2 rows, cols {jg, jg+16} per gate.
// Barrier: per row-group (16 CTAs sharing rt) — row groups are independent.

#define WSTR 516
#define REC_SMEM ((96 * WSTR + 16 * HH) * 4)   // 198144 + 32768 = 230912 B

__global__ void __launch_bounds__(128, 1) gru_kernel(const float* __restrict__ Wh,
                                                     const float* __restrict__ bias,
                                                     float* __restrict__ out) {
    extern __shared__ float sm[];
    float* Ws  = sm;                 // [96][516]
    float* hsm = sm + 96 * WSTR;     // [16][512]

    const int tid = threadIdx.x;
    const int ct = blockIdx.x & 15;
    const int rt = blockIdx.x >> 4;
    const int jbase = ct * 32;

    // Stage W_h slice transposed: Ws[c][k] = Wh[k][g*512 + jbase + j], c = g*32+j
    for (int i = tid; i < 96 * HH; i += 128) {
        int c = i % 96;
        int k = i / 96;
        Ws[c * WSTR + k] = Wh[(size_t)k * G3 + (c >> 5) * HH + jbase + (c & 31)];
    }

    const int rg = tid >> 4;          // 0..7
    const int jg = tid & 15;          // 0..15
    const int r0 = rg * 2;

    float bh[3][2];
#pragma unroll
    for (int g = 0; g < 3; ++g) {
        bh[g][0] = bias[G3 + g * HH + jbase + jg];
        bh[g][1] = bias[G3 + g * HH + jbase + jg + 16];
    }

    // W column base pointers (6 columns)
    const float* Wp[3][2];
#pragma unroll
    for (int g = 0; g < 3; ++g) {
        Wp[g][0] = Ws + (g * 32 + jg) * WSTR;
        Wp[g][1] = Ws + (g * 32 + jg + 16) * WSTR;
    }
    __syncthreads();

    const int b0 = rt * 16;
    unsigned* bar = &g_bar[rt * 64];

    for (int s = 0; s < SS; ++s) {
        const float* hin = g_h[s & 1];
        float* hout = g_h[(s + 1) & 1];

        // ---- prefetch x_proj contributions for this step ----
        float xv[2][3][2];
#pragma unroll
        for (int ri = 0; ri < 2; ++ri) {
            const float* xp = g_xproj + ((size_t)(b0 + r0 + ri) * SS + s) * G3;
#pragma unroll
            for (int g = 0; g < 3; ++g) {
                xv[ri][g][0] = __ldg(xp + g * HH + jbase + jg);
                xv[ri][g][1] = __ldg(xp + g * HH + jbase + jg + 16);
            }
        }

        // ---- stage h tile (16 x 512) from L2 ----
#pragma unroll
        for (int t = 0; t < 16; ++t) {
            int idx = (t * 128 + tid) * 4;
            float4 v = __ldcg((const float4*)(hin + (size_t)b0 * HH + idx));
            *(float4*)(hsm + idx) = v;
        }
        __syncthreads();

        // ---- GEMM: acc lanes split even/odd k; bias seeded in BOTH rows ----
        unsigned long long acc[2][3][2];
#pragma unroll
        for (int g = 0; g < 3; ++g) {
#pragma unroll
            for (int t = 0; t < 2; ++t) {
                acc[0][g][t] = pack2(bh[g][t], 0.0f);
                acc[1][g][t] = pack2(bh[g][t], 0.0f);
            }
        }

        const float* hr0 = hsm + r0 * HH;
        const float* hr1 = hr0 + HH;

#pragma unroll 2
        for (int k = 0; k < HH; k += 4) {
            ulonglong2 h0 = *(const ulonglong2*)(hr0 + k);
            ulonglong2 h1 = *(const ulonglong2*)(hr1 + k);
#pragma unroll
            for (int g = 0; g < 3; ++g) {
#pragma unroll
                for (int t = 0; t < 2; ++t) {
                    ulonglong2 w = *(const ulonglong2*)(Wp[g][t] + k);
                    acc[0][g][t] = ffma2(h0.x, w.x, acc[0][g][t]);
                    acc[0][g][t] = ffma2(h0.y, w.y, acc[0][g][t]);
                    acc[1][g][t] = ffma2(h1.x, w.x, acc[1][g][t]);
                    acc[1][g][t] = ffma2(h1.y, w.y, acc[1][g][t]);
                }
            }
        }

        // ---- gates + state update + outputs ----
#pragma unroll
        for (int ri = 0; ri < 2; ++ri) {
            int b = b0 + r0 + ri;
            const float* hrow = hsm + (r0 + ri) * HH;
#pragma unroll
            for (int t = 0; t < 2; ++t) {
                int j = jbase + jg + 16 * t;
                float hr = sum2(acc[ri][0][t]);
                float hz = sum2(acc[ri][1][t]);
                float hn = sum2(acc[ri][2][t]);
                float rr = 1.0f / (1.0f + expf(-(xv[ri][0][t] + hr)));
                float zz = 1.0f / (1.0f + expf(-(xv[ri][1][t] + hz)));
                float nn = tanhf(xv[ri][2][t] + rr * hn);
                float hold = hrow[j];
                float hnew = (1.0f - zz) * nn + zz * hold;
                out[((size_t)b * SS + s) * HH + j] = hnew;
                hout[(size_t)b * HH + j] = hnew;
                if (s == SS - 1)
                    out[(size_t)BB * SS * HH + (size_t)b * HH + j] = hnew;
            }
        }

        // ---- row-group barrier (16 CTAs) ----
        __threadfence();
        __syncthreads();
        if (tid == 0) {
            atomicAdd(bar, 1u);
            unsigned tgt = 16u * (unsigned)(s + 1);
            while (*(volatile unsigned*)bar < tgt) { }
        }
        __syncthreads();
        __threadfence();
    }
}

// ---------------- launch ----------------
extern "C" void kernel_launch(void* const* d_in, const int* in_sizes, int n_in,
                              void* d_out, int out_size) {
    const float* inputs = (const float*)d_in[0];   // (B, S, I)
    const float* W_in   = (const float*)d_in[1];   // (I, 3H)
    const float* W_h    = (const float*)d_in[2];   // (H, 3H)
    const float* bias   = (const float*)d_in[3];   // (6H,)
    float* out = (float*)d_out;

    init_kernel<<<64, 256>>>();

    dim3 xgrid(G3 / XPN, (BB * SS) / XPM);   // (24, 1024)
    xproj_kernel<<<xgrid, 256>>>(inputs, W_in, bias);

    cudaFuncSetAttribute(gru_kernel, cudaFuncAttributeMaxDynamicSharedMemorySize, REC_SMEM);
    gru_kernel<<<128, 128, REC_SMEM>>>(W_h, bias, out);
}

// round 5
// speedup vs baseline: 1.2319x; 1.1458x over previous
#include <cuda_runtime.h>
#include <math.h>
#include <stdint.h>

#define BB 128
#define SS 1024
#define II 256
#define HH 512
#define G3 1536   // 3*H

// ---------------- device scratch ----------------
__device__ float g_xproj[(size_t)BB * SS * G3];   // (B, S, 3H)
__device__ float g_h[2][BB * HH];                 // double-buffered hidden state
__device__ unsigned g_bar[8 * 64];                // per-row-group barrier counters

// ---------------- f32x2 helpers ----------------
__device__ __forceinline__ unsigned long long ffma2(unsigned long long a,
                                                    unsigned long long b,
                                                    unsigned long long c) {
    unsigned long long d;
    asm("fma.rn.f32x2 %0, %1, %2, %3;" : "=l"(d) : "l"(a), "l"(b), "l"(c));
    return d;
}
__device__ __forceinline__ unsigned long long pack2(float x, float y) {
    unsigned long long d;
    asm("mov.b64 %0, {%1, %2};" : "=l"(d) : "f"(x), "f"(y));
    return d;
}
__device__ __forceinline__ float sum2(unsigned long long v) {
    float a, b;
    asm("mov.b64 {%0, %1}, %2;" : "=f"(a), "=f"(b) : "l"(v));
    return a + b;
}

// ---------------- x_proj GEMM: (B*S, I) x (I, 3H) + b_in, f32x2 k-split ----------------
// CTA (0,0) additionally zeroes h0 and ALL barrier counters (init merged here).
#define XPM 128
#define XPN 64
#define XPK 16

__global__ void __launch_bounds__(256, 2) xproj_kernel(const float* __restrict__ A,
                                                       const float* __restrict__ W,
                                                       const float* __restrict__ bias) {
    // merged init (stream order guarantees visibility to gru_kernel)
    if (blockIdx.x == 0 && blockIdx.y == 0) {
        int t = threadIdx.x;
        for (int i = t; i < 8 * 64; i += 256)       // FIX: cover all 512 counters
            g_bar[i] = 0u;
        for (int i = t; i < BB * HH / 4; i += 256)
            ((float4*)g_h[0])[i] = make_float4(0.f, 0.f, 0.f, 0.f);
    }

    __shared__ float As[XPM * XPK];     // [m][k], stride 16
    __shared__ float Wt[XPN * 18];      // [n][k] transposed, stride 18

    const int m0 = blockIdx.y * XPM;
    const int n0 = blockIdx.x * XPN;
    const int tid = threadIdx.x;
    const int tm = tid >> 4;
    const int tn = tid & 15;
    const int m_base = tm * 8;

    unsigned long long acc[8][4];
#pragma unroll
    for (int i = 0; i < 8; ++i)
#pragma unroll
        for (int j = 0; j < 4; ++j) acc[i][j] = 0ull;

    const int sa_m = tid >> 2;
    const int sa_k = (tid & 3) << 2;
    const int sw_k = tid >> 4;
    const int sw_n = (tid & 15) << 2;

    for (int k0 = 0; k0 < II; k0 += XPK) {
#pragma unroll
        for (int q = 0; q < 2; ++q) {
            int m = sa_m + q * 64;
            *(float4*)&As[m * 16 + sa_k] =
                *(const float4*)(A + (size_t)(m0 + m) * II + k0 + sa_k);
        }
        {
            float4 w = *(const float4*)(W + (size_t)(k0 + sw_k) * G3 + n0 + sw_n);
            Wt[(sw_n + 0) * 18 + sw_k] = w.x;
            Wt[(sw_n + 1) * 18 + sw_k] = w.y;
            Wt[(sw_n + 2) * 18 + sw_k] = w.z;
            Wt[(sw_n + 3) * 18 + sw_k] = w.w;
        }
        __syncthreads();

#pragma unroll
        for (int kk = 0; kk < XPK; kk += 4) {
            ulonglong2 av[8];
#pragma unroll
            for (int i = 0; i < 8; ++i)
                av[i] = *(const ulonglong2*)&As[(m_base + i) * 16 + kk];
#pragma unroll
            for (int j = 0; j < 4; ++j) {
                const float* wp = &Wt[(tn + 16 * j) * 18 + kk];
                unsigned long long w0 = *(const unsigned long long*)(wp);
                unsigned long long w1 = *(const unsigned long long*)(wp + 2);
#pragma unroll
                for (int i = 0; i < 8; ++i) {
                    acc[i][j] = ffma2(av[i].x, w0, acc[i][j]);
                    acc[i][j] = ffma2(av[i].y, w1, acc[i][j]);
                }
            }
        }
        __syncthreads();
    }

    float bb[4];
#pragma unroll
    for (int j = 0; j < 4; ++j) bb[j] = bias[n0 + tn + 16 * j];

#pragma unroll
    for (int i = 0; i < 8; ++i) {
        float* orow = g_xproj + (size_t)(m0 + m_base + i) * G3 + n0 + tn;
#pragma unroll
        for (int j = 0; j < 4; ++j)
            orow[16 * j] = sum2(acc[i][j]) + bb[j];
    }
}

// ---------------- persistent GRU recurrence ----------------
// 128 CTAs = 8 row-tiles (16 batch rows) x 16 col-tiles (32 hidden cols x 3 gates).
// W_h slice in SMEM as k-pair-interleaved 64-bit elements: Ws2[k2*96 + c],
//   element = (W[2k2][col], W[2k2+1][col]),  c = gate*32 + j_local.
// Thread (rg 0..3, jg 0..31): 4 batch rows (r0..r0+3), 1 j per gate.
//   -> W LDS.64 fully coalesced (256B span, no conflicts); h LDS.128 broadcast.

#define REC_SMEM (96 * 256 * 8 + 16 * HH * 4)   // 196608 + 32768 = 229376 B

__global__ void __launch_bounds__(128, 1) gru_kernel(const float* __restrict__ Wh,
                                                     const float* __restrict__ bias,
                                                     float* __restrict__ out) {
    extern __shared__ float sm[];
    unsigned long long* Ws2 = (unsigned long long*)sm;   // [256][96]
    float* hsm = sm + 96 * 256 * 2;                      // [16][512]

    const int tid = threadIdx.x;
    const int ct = blockIdx.x & 15;
    const int rt = blockIdx.x >> 4;
    const int jbase = ct * 32;

    // Stage W_h slice: Ws2[k2*96 + c] = pack(Wh[2k2][col], Wh[2k2+1][col])
    for (int i = tid; i < 96 * 256; i += 128) {
        int k2 = i / 96;
        int c = i - k2 * 96;
        int col = (c >> 5) * HH + jbase + (c & 31);
        float w0 = Wh[(size_t)(2 * k2) * G3 + col];
        float w1 = Wh[(size_t)(2 * k2 + 1) * G3 + col];
        Ws2[i] = pack2(w0, w1);
    }

    const int rg = tid >> 5;          // 0..3
    const int jg = tid & 31;          // 0..31
    const int r0 = rg * 4;
    const int j = jbase + jg;

    float bh[3];
#pragma unroll
    for (int g = 0; g < 3; ++g)
        bh[g] = bias[G3 + g * HH + j];

    __syncthreads();

    const int b0 = rt * 16;
    unsigned* bar = &g_bar[rt * 64];

    for (int s = 0; s < SS; ++s) {
        const float* hin = g_h[s & 1];
        float* hout = g_h[(s + 1) & 1];

        // ---- prefetch x_proj contributions (consumed only in epilogue) ----
        float xv[4][3];
#pragma unroll
        for (int ri = 0; ri < 4; ++ri) {
            const float* xp = g_xproj + ((size_t)(b0 + r0 + ri) * SS + s) * G3;
#pragma unroll
            for (int g = 0; g < 3; ++g)
                xv[ri][g] = __ldg(xp + g * HH + j);
        }

        // ---- stage h tile (16 x 512) from L2 ----
#pragma unroll
        for (int t = 0; t < 16; ++t) {
            int idx = (t * 128 + tid) * 4;
            float4 v = __ldcg((const float4*)(hin + (size_t)b0 * HH + idx));
            *(float4*)(hsm + idx) = v;
        }
        __syncthreads();

        // ---- GEMM: 4 rows x 3 gates, f32x2 even/odd-k lanes ----
        unsigned long long acc[4][3];
#pragma unroll
        for (int ri = 0; ri < 4; ++ri)
#pragma unroll
            for (int g = 0; g < 3; ++g)
                acc[ri][g] = pack2(bh[g], 0.0f);

        const float* hr = hsm + r0 * HH;

#pragma unroll 2
        for (int k = 0; k < HH; k += 4) {
            ulonglong2 hv[4];
#pragma unroll
            for (int ri = 0; ri < 4; ++ri)
                hv[ri] = *(const ulonglong2*)(hr + ri * HH + k);

            const unsigned long long* wrow = Ws2 + (k >> 1) * 96 + jg;
#pragma unroll
            for (int g = 0; g < 3; ++g) {
                unsigned long long wa = wrow[g * 32];        // k pair (k, k+1)
                unsigned long long wb = wrow[96 + g * 32];   // k pair (k+2, k+3)
#pragma unroll
                for (int ri = 0; ri < 4; ++ri) {
                    acc[ri][g] = ffma2(hv[ri].x, wa, acc[ri][g]);
                    acc[ri][g] = ffma2(hv[ri].y, wb, acc[ri][g]);
                }
            }
        }

        // ---- gates + state update + outputs ----
#pragma unroll
        for (int ri = 0; ri < 4; ++ri) {
            int b = b0 + r0 + ri;
            float hrg = sum2(acc[ri][0]);
            float hzg = sum2(acc[ri][1]);
            float hng = sum2(acc[ri][2]);
            float rr = 1.0f / (1.0f + expf(-(xv[ri][0] + hrg)));
            float zz = 1.0f / (1.0f + expf(-(xv[ri][1] + hzg)));
            float nn = tanhf(xv[ri][2] + rr * hng);
            float hold = hsm[(r0 + ri) * HH + j];
            float hnew = (1.0f - zz) * nn + zz * hold;
            out[((size_t)b * SS + s) * HH + j] = hnew;
            hout[(size_t)b * HH + j] = hnew;
            if (s == SS - 1)
                out[(size_t)BB * SS * HH + (size_t)b * HH + j] = hnew;
        }

        // ---- row-group barrier (16 CTAs) ----
        __threadfence();
        __syncthreads();
        if (tid == 0) {
            atomicAdd(bar, 1u);
            unsigned tgt = 16u * (unsigned)(s + 1);
            while (*(volatile unsigned*)bar < tgt) { }
        }
        __syncthreads();
        __threadfence();
    }
}

// ---------------- launch ----------------
extern "C" void kernel_launch(void* const* d_in, const int* in_sizes, int n_in,
                              void* d_out, int out_size) {
    const float* inputs = (const float*)d_in[0];   // (B, S, I)
    const float* W_in   = (const float*)d_in[1];   // (I, 3H)
    const float* W_h    = (const float*)d_in[2];   // (H, 3H)
    const float* bias   = (const float*)d_in[3];   // (6H,)
    float* out = (float*)d_out;

    dim3 xgrid(G3 / XPN, (BB * SS) / XPM);   // (24, 1024)
    xproj_kernel<<<xgrid, 256>>>(inputs, W_in, bias);

    cudaFuncSetAttribute(gru_kernel, cudaFuncAttributeMaxDynamicSharedMemorySize, REC_SMEM);
    gru_kernel<<<128, 128, REC_SMEM>>>(W_h, bias, out);
}